// round 3
// baseline (speedup 1.0000x reference)
#include <cuda_runtime.h>
#include <cstdint>

#define NPROP 1024
#define NCLS  81
#define NC1   80
#define BIMG  2
#define DOUT  100
#define SCORE_TH 0.05f
#define NMS_TH   0.5f
#define IMG_MAX  1023.0f   // W - TO_REMOVE
#define NCAND (NC1 * NPROP)

// ---------------- device scratch (no allocations allowed) ----------------
__device__ float  g_probs[BIMG * NPROP * NCLS];
__device__ int    g_cand_cnt[BIMG];
__device__ float  g_cand_score[BIMG][NCAND];
__device__ int    g_cand_flat [BIMG][NCAND];
__device__ float4 g_cand_box  [BIMG][NCAND];

// ---------------- kernel 1: softmax + counter reset ----------------
// one warp per (b, n) row of 81 logits
__global__ void k_softmax(const float* __restrict__ logits) {
    if (blockIdx.x == 0 && threadIdx.x < BIMG) g_cand_cnt[threadIdx.x] = 0;
    int warp = (blockIdx.x * blockDim.x + threadIdx.x) >> 5;
    int lane = threadIdx.x & 31;
    if (warp >= BIMG * NPROP) return;
    const float* row = logits + (size_t)warp * NCLS;
    float v0 = row[lane];                                   // lane < 32 < 81
    float v1 = (lane + 32 < NCLS) ? row[lane + 32] : -1e30f;
    float v2 = (lane + 64 < NCLS) ? row[lane + 64] : -1e30f;
    float m = fmaxf(v0, fmaxf(v1, v2));
    #pragma unroll
    for (int o = 16; o; o >>= 1) m = fmaxf(m, __shfl_xor_sync(~0u, m, o));
    float e0 = expf(v0 - m);
    float e1 = (lane + 32 < NCLS) ? expf(v1 - m) : 0.f;
    float e2 = (lane + 64 < NCLS) ? expf(v2 - m) : 0.f;
    float s = e0 + e1 + e2;
    #pragma unroll
    for (int o = 16; o; o >>= 1) s += __shfl_xor_sync(~0u, s, o);
    float inv = 1.f / s;
    float* out = g_probs + (size_t)warp * NCLS;
    out[lane] = e0 * inv;
    if (lane + 32 < NCLS) out[lane + 32] = e1 * inv;
    if (lane + 64 < NCLS) out[lane + 64] = e2 * inv;
}

// ---------------- kernel 2: per-(image, class) compact + sort + decode + NMS ----------------
__global__ void __launch_bounds__(256) k_nms(const float* __restrict__ reg,
                                             const float* __restrict__ props) {
    const int NT = 256;
    int b  = blockIdx.x / NC1;
    int c0 = blockIdx.x % NC1;      // 0-based over classes 1..80
    int tid = threadIdx.x;

    __shared__ unsigned long long skey[NPROP];
    __shared__ float4 sbox[NPROP];
    __shared__ unsigned char skeep[NPROP];
    __shared__ int scnt;
    if (tid == 0) scnt = 0;
    __syncthreads();

    // compact valid candidates; key = (score_bits << 32) | (1023 - n)
    // (scores positive -> float bits monotone; low word gives n-ascending tie-break
    //  under descending sort, matching stable argsort(-scores))
    const float* pr = g_probs + (size_t)(b * NPROP) * NCLS + (c0 + 1);
    for (int n = tid; n < NPROP; n += NT) {
        float s = pr[(size_t)n * NCLS];
        if (s > SCORE_TH) {
            int p = atomicAdd(&scnt, 1);
            skey[p] = ((unsigned long long)__float_as_uint(s) << 32)
                    | (unsigned)(NPROP - 1 - n);
        }
    }
    __syncthreads();
    int M = scnt;
    if (M == 0) return;

    // bitonic sort, descending; pad with 0 sentinels
    int P = 1; while (P < M) P <<= 1;
    for (int i = M + tid; i < P; i += NT) skey[i] = 0ull;
    __syncthreads();
    for (int k = 2; k <= P; k <<= 1) {
        for (int j = k >> 1; j > 0; j >>= 1) {
            for (int i = tid; i < P; i += NT) {
                int ixj = i ^ j;
                if (ixj > i) {
                    bool up = ((i & k) != 0);           // descending overall
                    unsigned long long a = skey[i], c = skey[ixj];
                    if ((a > c) == up) { skey[i] = c; skey[ixj] = a; }
                }
            }
            __syncthreads();
        }
    }

    // decode the M sorted candidates
    const float BBOX_CLIP = 4.135166556742356f;   // log(1000/16)
    for (int i = tid; i < M; i += NT) {
        int n = NPROP - 1 - (int)(skey[i] & 0xFFFFFFFFu);
        const float* p4 = props + (size_t)(b * NPROP + n) * 4;
        float x1 = p4[0], y1 = p4[1], x2 = p4[2], y2 = p4[3];
        float w  = x2 - x1 + 1.f, h = y2 - y1 + 1.f;
        float cx = x1 + 0.5f * w,  cy = y1 + 0.5f * h;
        const float* r4 = reg + ((size_t)(b * NPROP + n) * NCLS + (c0 + 1)) * 4;
        float dx = r4[0] / 10.f, dy = r4[1] / 10.f;
        float dw = fminf(r4[2] / 5.f, BBOX_CLIP);
        float dh = fminf(r4[3] / 5.f, BBOX_CLIP);
        float pcx = dx * w + cx, pcy = dy * h + cy;
        float pw = expf(dw) * w, ph = expf(dh) * h;
        float nx1 = fminf(fmaxf(pcx - 0.5f * pw, 0.f), IMG_MAX);
        float ny1 = fminf(fmaxf(pcy - 0.5f * ph, 0.f), IMG_MAX);
        float nx2 = fminf(fmaxf(pcx + 0.5f * pw - 1.f, 0.f), IMG_MAX);
        float ny2 = fminf(fmaxf(pcy + 0.5f * ph - 1.f, 0.f), IMG_MAX);
        sbox[i] = make_float4(nx1, ny1, nx2, ny2);
        skeep[i] = 1;
    }
    __syncthreads();

    // greedy NMS (score-descending order); IoU uses legacy +1 convention
    for (int i = 0; i < M - 1; ++i) {
        if (skeep[i]) {
            float4 bi = sbox[i];
            float ai = (bi.z - bi.x + 1.f) * (bi.w - bi.y + 1.f);
            for (int j = i + 1 + tid; j < M; j += NT) {
                if (!skeep[j]) continue;
                float4 bj = sbox[j];
                float aj = (bj.z - bj.x + 1.f) * (bj.w - bj.y + 1.f);
                float ix = fmaxf(fminf(bi.z, bj.z) - fmaxf(bi.x, bj.x) + 1.f, 0.f);
                float iy = fmaxf(fminf(bi.w, bj.w) - fmaxf(bi.y, bj.y) + 1.f, 0.f);
                float inter = ix * iy;
                if (inter / (ai + aj - inter) > NMS_TH) skeep[j] = 0;
            }
        }
        __syncthreads();
    }

    // append survivors to per-image candidate list
    for (int i = tid; i < M; i += NT) {
        if (!skeep[i]) continue;
        unsigned long long key = skey[i];
        int n = NPROP - 1 - (int)(key & 0xFFFFFFFFu);
        int pos = atomicAdd(&g_cand_cnt[b], 1);
        g_cand_score[b][pos] = __uint_as_float((unsigned)(key >> 32));
        g_cand_flat [b][pos] = c0 * NPROP + n;    // matches lax.top_k flat index
        g_cand_box  [b][pos] = sbox[i];
    }
}

// ---------------- kernel 3: per-image top-100 + output ----------------
// Output layout (float32): boxes [B,D,4] | scores [B,D] | labels [B,D]
__global__ void __launch_bounds__(256) k_topk(float* __restrict__ out) {
    const int NT = 256;
    int b = blockIdx.x;
    int tid = threadIdx.x;
    __shared__ unsigned long long rk[NT];
    __shared__ int ri[NT];
    __shared__ unsigned staken[(NCAND + 31) / 32];
    int K = g_cand_cnt[b];
    for (int i = tid; i < (K + 31) / 32; i += NT) staken[i] = 0;
    __syncthreads();

    for (int d = 0; d < DOUT; ++d) {
        unsigned long long best = 0; int bidx = -1;
        for (int i = tid; i < K; i += NT) {
            if ((staken[i >> 5] >> (i & 31)) & 1u) continue;
            // key: score desc, then flat asc (lower flat wins ties, like lax.top_k)
            unsigned long long key =
                ((unsigned long long)__float_as_uint(g_cand_score[b][i]) << 32)
                | (unsigned)(~(unsigned)g_cand_flat[b][i]);
            if (key > best) { best = key; bidx = i; }
        }
        rk[tid] = best; ri[tid] = bidx;
        __syncthreads();
        for (int o = NT / 2; o > 0; o >>= 1) {
            if (tid < o && rk[tid + o] > rk[tid]) { rk[tid] = rk[tid + o]; ri[tid] = ri[tid + o]; }
            __syncthreads();
        }
        if (tid == 0) {
            int w = ri[0];
            float4 bx = make_float4(0.f, 0.f, 0.f, 0.f);
            float sc = 0.f, lb = -1.f;
            if (w >= 0) {
                float sw = __uint_as_float((unsigned)(rk[0] >> 32));
                if (sw > SCORE_TH * 0.5f) {   // all real candidates > 0.05
                    staken[w >> 5] |= (1u << (w & 31));
                    bx = g_cand_box[b][w];
                    sc = sw;
                    lb = (float)(g_cand_flat[b][w] / NPROP + 1);
                }
            }
            float* ob = out + (size_t)(b * DOUT + d) * 4;
            ob[0] = bx.x; ob[1] = bx.y; ob[2] = bx.z; ob[3] = bx.w;
            out[BIMG * DOUT * 4 + b * DOUT + d] = sc;
            out[BIMG * DOUT * 4 + BIMG * DOUT + b * DOUT + d] = lb;
        }
        __syncthreads();
    }
}

// ---------------- launch ----------------
extern "C" void kernel_launch(void* const* d_in, const int* in_sizes, int n_in,
                              void* d_out, int out_size) {
    const float *logits = nullptr, *reg = nullptr, *props = nullptr;
    for (int i = 0; i < n_in; ++i) {
        if      (in_sizes[i] == BIMG * NPROP * NCLS)     logits = (const float*)d_in[i];
        else if (in_sizes[i] == BIMG * NPROP * NCLS * 4) reg    = (const float*)d_in[i];
        else if (in_sizes[i] == BIMG * NPROP * 4)        props  = (const float*)d_in[i];
    }
    // 2048 rows, 8 warps/block -> 256 blocks
    k_softmax<<<(BIMG * NPROP) / 8, 256>>>(logits);
    k_nms<<<BIMG * NC1, 256>>>(reg, props);
    k_topk<<<BIMG, 256>>>((float*)d_out);
}

// round 5
// speedup vs baseline: 2.2300x; 2.2300x over previous
#include <cuda_runtime.h>
#include <cstdint>

#define NPROP 1024
#define NCLS  81
#define NC1   80
#define BIMG  2
#define DOUT  100
#define SCORE_TH 0.05f
#define NMS_TH   0.5f
#define IMG_MAX  1023.0f   // W - TO_REMOVE
#define NCAND (NC1 * NPROP)
#define TOPK_P 4096        // fast-path capacity for final sort (32KB smem)

// ---------------- device scratch (no allocations allowed) ----------------
__device__ float2 g_rowstat[BIMG * NPROP];            // {rowmax, 1/sum(exp)}
__device__ int    g_cand_cnt[BIMG];
__device__ unsigned long long g_cand_key[BIMG][NCAND]; // (score_bits<<32)|~flat

// ---------------- shared decode helper (exact maskrcnn-benchmark math) ----
__device__ __forceinline__ float4 decode_box(const float* __restrict__ reg,
                                             const float* __restrict__ props,
                                             int b, int n, int c0) {
    const float BBOX_CLIP = 4.135166556742356f;   // log(1000/16)
    const float* p4 = props + (size_t)(b * NPROP + n) * 4;
    float x1 = p4[0], y1 = p4[1], x2 = p4[2], y2 = p4[3];
    float w  = x2 - x1 + 1.f, h = y2 - y1 + 1.f;
    float cx = x1 + 0.5f * w,  cy = y1 + 0.5f * h;
    const float* r4 = reg + ((size_t)(b * NPROP + n) * NCLS + (c0 + 1)) * 4;
    float dx = r4[0] / 10.f, dy = r4[1] / 10.f;
    float dw = fminf(r4[2] / 5.f, BBOX_CLIP);
    float dh = fminf(r4[3] / 5.f, BBOX_CLIP);
    float pcx = dx * w + cx, pcy = dy * h + cy;
    float pw = expf(dw) * w, ph = expf(dh) * h;
    float nx1 = fminf(fmaxf(pcx - 0.5f * pw, 0.f), IMG_MAX);
    float ny1 = fminf(fmaxf(pcy - 0.5f * ph, 0.f), IMG_MAX);
    float nx2 = fminf(fmaxf(pcx + 0.5f * pw - 1.f, 0.f), IMG_MAX);
    float ny2 = fminf(fmaxf(pcy + 0.5f * ph - 1.f, 0.f), IMG_MAX);
    return make_float4(nx1, ny1, nx2, ny2);
}

// ---------------- kernel 1: per-row softmax stats (max, 1/sum) ------------
// one warp per (b, n) row of 81 logits
__global__ void k_rowstat(const float* __restrict__ logits) {
    if (blockIdx.x == 0 && threadIdx.x < BIMG) g_cand_cnt[threadIdx.x] = 0;
    int warp = (blockIdx.x * blockDim.x + threadIdx.x) >> 5;
    int lane = threadIdx.x & 31;
    if (warp >= BIMG * NPROP) return;
    const float* row = logits + (size_t)warp * NCLS;
    float v0 = row[lane];
    float v1 = (lane + 32 < NCLS) ? row[lane + 32] : -1e30f;
    float v2 = (lane + 64 < NCLS) ? row[lane + 64] : -1e30f;
    float m = fmaxf(v0, fmaxf(v1, v2));
    #pragma unroll
    for (int o = 16; o; o >>= 1) m = fmaxf(m, __shfl_xor_sync(~0u, m, o));
    float e0 = expf(v0 - m);
    float e1 = (lane + 32 < NCLS) ? expf(v1 - m) : 0.f;
    float e2 = (lane + 64 < NCLS) ? expf(v2 - m) : 0.f;
    float s = e0 + e1 + e2;
    #pragma unroll
    for (int o = 16; o; o >>= 1) s += __shfl_xor_sync(~0u, s, o);
    if (lane == 0) g_rowstat[warp] = make_float2(m, 1.f / s);
}

// ---------------- kernel 2: per-(image, class) compact+sort+decode+NMS ----
__global__ void __launch_bounds__(256) k_nms(const float* __restrict__ logits,
                                             const float* __restrict__ reg,
                                             const float* __restrict__ props) {
    const int NT = 256;
    int b  = blockIdx.x / NC1;
    int c0 = blockIdx.x % NC1;      // 0-based over classes 1..80
    int tid = threadIdx.x;

    __shared__ unsigned long long skey[NPROP];
    __shared__ float4 sbox[NPROP];
    __shared__ unsigned char skeep[NPROP];
    __shared__ int scnt;
    if (tid == 0) scnt = 0;
    __syncthreads();

    // compact valid candidates; key = (score_bits << 32) | (1023 - n)
    const float*  lg = logits + (size_t)(b * NPROP) * NCLS + (c0 + 1);
    const float2* rs = g_rowstat + b * NPROP;
    for (int n = tid; n < NPROP; n += NT) {
        float2 st = rs[n];
        float s = expf(lg[(size_t)n * NCLS] - st.x) * st.y;
        if (s > SCORE_TH) {
            int p = atomicAdd(&scnt, 1);
            skey[p] = ((unsigned long long)__float_as_uint(s) << 32)
                    | (unsigned)(NPROP - 1 - n);
        }
    }
    __syncthreads();
    int M = scnt;
    if (M == 0) return;

    // bitonic sort, descending; pad with 0 sentinels
    int P = 1; while (P < M) P <<= 1;
    for (int i = M + tid; i < P; i += NT) skey[i] = 0ull;
    __syncthreads();
    for (int k = 2; k <= P; k <<= 1) {
        for (int j = k >> 1; j > 0; j >>= 1) {
            for (int i = tid; i < P; i += NT) {
                int ixj = i ^ j;
                if (ixj > i) {
                    bool up = ((i & k) != 0);           // descending overall
                    unsigned long long a = skey[i], c = skey[ixj];
                    if ((a > c) == up) { skey[i] = c; skey[ixj] = a; }
                }
            }
            __syncthreads();
        }
    }

    // decode the M sorted candidates
    for (int i = tid; i < M; i += NT) {
        int n = NPROP - 1 - (int)(skey[i] & 0xFFFFFFFFu);
        sbox[i] = decode_box(reg, props, b, n, c0);
        skeep[i] = 1;
    }
    __syncthreads();

    // greedy NMS (score-descending); IoU uses legacy +1 convention
    for (int i = 0; i < M - 1; ++i) {
        if (skeep[i]) {
            float4 bi = sbox[i];
            float ai = (bi.z - bi.x + 1.f) * (bi.w - bi.y + 1.f);
            for (int j = i + 1 + tid; j < M; j += NT) {
                if (!skeep[j]) continue;
                float4 bj = sbox[j];
                float aj = (bj.z - bj.x + 1.f) * (bj.w - bj.y + 1.f);
                float ix = fmaxf(fminf(bi.z, bj.z) - fmaxf(bi.x, bj.x) + 1.f, 0.f);
                float iy = fmaxf(fminf(bi.w, bj.w) - fmaxf(bi.y, bj.y) + 1.f, 0.f);
                float inter = ix * iy;
                if (inter / (ai + aj - inter) > NMS_TH) skeep[j] = 0;
            }
        }
        __syncthreads();
    }

    // append survivor keys to per-image candidate list
    for (int i = tid; i < M; i += NT) {
        if (!skeep[i]) continue;
        unsigned long long key = skey[i];
        int n = NPROP - 1 - (int)(key & 0xFFFFFFFFu);
        unsigned flat = (unsigned)(c0 * NPROP + n);     // matches lax.top_k flat idx
        int pos = atomicAdd(&g_cand_cnt[b], 1);
        g_cand_key[b][pos] = (key & 0xFFFFFFFF00000000ull) | (unsigned)(~flat);
    }
}

// ---------------- kernel 3: per-image top-100 via bitonic sort ------------
// Output layout (float32): boxes [B,D,4] | scores [B,D] | labels [B,D]
__global__ void __launch_bounds__(512) k_topk(const float* __restrict__ reg,
                                              const float* __restrict__ props,
                                              float* __restrict__ out) {
    const int NT = 512;
    int b = blockIdx.x;
    int tid = threadIdx.x;
    __shared__ unsigned long long sk[TOPK_P];
    __shared__ unsigned long long rk[NT];
    __shared__ int ri[NT];
    int K = g_cand_cnt[b];

    if (K <= TOPK_P) {
        // ---- fast path: sort all candidates in shared, take first 100 ----
        for (int i = tid; i < TOPK_P; i += NT)
            sk[i] = (i < K) ? g_cand_key[b][i] : 0ull;
        __syncthreads();
        int P = 2; while (P < K) P <<= 1;
        for (int k = 2; k <= P; k <<= 1) {
            for (int j = k >> 1; j > 0; j >>= 1) {
                for (int i = tid; i < P; i += NT) {
                    int ixj = i ^ j;
                    if (ixj > i) {
                        bool up = ((i & k) != 0);       // descending overall
                        unsigned long long a = sk[i], c = sk[ixj];
                        if ((a > c) == up) { sk[i] = c; sk[ixj] = a; }
                    }
                }
                __syncthreads();
            }
        }
    } else {
        // ---- fallback (never expected): iterative selection into sk[0..D)
        for (int d = 0; d < DOUT; ++d) {
            unsigned long long best = 0; int bidx = -1;
            for (int i = tid; i < K; i += NT) {
                unsigned long long key = g_cand_key[b][i];
                if (key > best) { best = key; bidx = i; }
            }
            rk[tid] = best; ri[tid] = bidx;
            __syncthreads();
            for (int o = NT / 2; o > 0; o >>= 1) {
                if (tid < o && rk[tid + o] > rk[tid]) { rk[tid] = rk[tid + o]; ri[tid] = ri[tid + o]; }
                __syncthreads();
            }
            if (tid == 0) {
                sk[d] = rk[0];
                if (ri[0] >= 0) g_cand_key[b][ri[0]] = 0ull;  // mark taken (k2 rebuilds each run)
            }
            __syncthreads();
        }
    }

    // ---- emit top-100 ----
    if (tid < DOUT) {
        unsigned long long key = (tid < K || K > TOPK_P) ? sk[tid] : 0ull;
        float4 bx = make_float4(0.f, 0.f, 0.f, 0.f);
        float sc = 0.f, lb = -1.f;
        if (key != 0ull) {
            unsigned flat = ~(unsigned)(key & 0xFFFFFFFFu);
            int c0 = flat / NPROP, n = flat % NPROP;
            bx = decode_box(reg, props, b, n, c0);
            sc = __uint_as_float((unsigned)(key >> 32));
            lb = (float)(c0 + 1);
        }
        float* ob = out + (size_t)(b * DOUT + tid) * 4;
        ob[0] = bx.x; ob[1] = bx.y; ob[2] = bx.z; ob[3] = bx.w;
        out[BIMG * DOUT * 4 + b * DOUT + tid] = sc;
        out[BIMG * DOUT * 4 + BIMG * DOUT + b * DOUT + tid] = lb;
    }
}

// ---------------- launch ----------------
extern "C" void kernel_launch(void* const* d_in, const int* in_sizes, int n_in,
                              void* d_out, int out_size) {
    const float *logits = nullptr, *reg = nullptr, *props = nullptr;
    for (int i = 0; i < n_in; ++i) {
        if      (in_sizes[i] == BIMG * NPROP * NCLS)     logits = (const float*)d_in[i];
        else if (in_sizes[i] == BIMG * NPROP * NCLS * 4) reg    = (const float*)d_in[i];
        else if (in_sizes[i] == BIMG * NPROP * 4)        props  = (const float*)d_in[i];
    }
    k_rowstat<<<(BIMG * NPROP) / 8, 256>>>(logits);        // 1 warp / row
    k_nms<<<BIMG * NC1, 256>>>(logits, reg, props);
    k_topk<<<BIMG, 512>>>(reg, props, (float*)d_out);
}